// round 5
// baseline (speedup 1.0000x reference)
#include <cuda_runtime.h>
#include <cstdint>

// EmbeddingWithDropout:
//   out[t, :] = weight[x[t], :] * ((u[x[t]] >= 0.1f) ? (1.0f/0.9f) : 0.0f)
// x: int32 [131072], weight: f32 [100000,128], u: f32 [100000], out: f32 [131072,128]
//
// One warp handles T=8 consecutive tokens; each lane owns one float4 (16 B) of the
// 128-wide row (32 x 16 B = 512 B, coalesced gather + store).
//
// Round-4 changes:
//  * __launch_bounds__(256, 4): allow 64 regs/thread so ptxas can keep all 8
//    float4 gathers (32 dest regs) in flight. R3's default reg target (32) forced
//    gather->store serialization (MLP_eff ~2-3, latency-bound at DRAM=35%).
//  * u-loads and weight-gathers issued in ONE wave (both depend only on rows[]):
//    2 dependent memory waves per 8 tokens instead of 3, 16 loads outstanding.

#define TOK_PER_WARP 8

__global__ void __launch_bounds__(256, 4)
embedding_dropout_kernel(const int* __restrict__ x,
                         const float4* __restrict__ weight,   // [vocab*32] float4
                         const float* __restrict__ u,         // [vocab]
                         float4* __restrict__ out,            // [n_tok*32] float4
                         int n_tok)
{
    const int gtid = blockIdx.x * blockDim.x + threadIdx.x;
    const int warp = gtid >> 5;
    const int lane = threadIdx.x & 31;
    const int base = warp * TOK_PER_WARP;
    if (base >= n_tok) return;

    if (base + TOK_PER_WARP <= n_tok) {
        // ---- Wave 1: 8 independent index loads (uniform broadcast) ----
        int rows[TOK_PER_WARP];
        #pragma unroll
        for (int i = 0; i < TOK_PER_WARP; i++)
            rows[i] = __ldg(&x[base + i]);

        // ---- Wave 2: 8 u-loads + 8 row-gathers, all independent, issued together ----
        float uv[TOK_PER_WARP];
        float4 v[TOK_PER_WARP];
        #pragma unroll
        for (int i = 0; i < TOK_PER_WARP; i++) {
            uv[i] = __ldg(&u[rows[i]]);
            v[i]  = __ldg(&weight[(size_t)rows[i] * 32 + lane]);
        }

        // ---- Scale + streaming store ----
        #pragma unroll
        for (int i = 0; i < TOK_PER_WARP; i++) {
            const float keep = (uv[i] >= 0.1f) ? (1.0f / 0.9f) : 0.0f;
            v[i].x *= keep;
            v[i].y *= keep;
            v[i].z *= keep;
            v[i].w *= keep;
            __stcs(&out[(size_t)(base + i) * 32 + lane], v[i]);
        }
    } else {
        // ---- Tail path ----
        for (int i = 0; base + i < n_tok; i++) {
            const int row = __ldg(&x[base + i]);
            const float keep = (__ldg(&u[row]) >= 0.1f) ? (1.0f / 0.9f) : 0.0f;
            float4 v = __ldg(&weight[(size_t)row * 32 + lane]);
            v.x *= keep; v.y *= keep; v.z *= keep; v.w *= keep;
            __stcs(&out[(size_t)(base + i) * 32 + lane], v);
        }
    }
}

extern "C" void kernel_launch(void* const* d_in, const int* in_sizes, int n_in,
                              void* d_out, int out_size)
{
    const int*    x      = (const int*)d_in[0];
    const float4* weight = (const float4*)d_in[1];
    const float*  u      = (const float*)d_in[2];
    float4*       out    = (float4*)d_out;

    const int n_tok = in_sizes[0];                            // 131072
    const int threads = 256;                                  // 8 warps/block
    const int tok_per_block = (threads / 32) * TOK_PER_WARP;  // 64
    const int blocks = (n_tok + tok_per_block - 1) / tok_per_block;

    embedding_dropout_kernel<<<blocks, threads>>>(x, weight, u, out, n_tok);
}